// round 10
// baseline (speedup 1.0000x reference)
#include <cuda_runtime.h>
#include <cuda_bf16.h>
#include <cstdint>

// Problem constants
#define NROWS   200000
#define FEAT    256
#define NCLASS  1000
#define NIMG    64
#define KPI     100
#define SLOTS   512            // padded rows-per-class capacity (max actual ~270)
#define CPAD    32             // cursor padding: 1 counter per 128B L2 line
#define COOC_RPB 4

// Fused-kernel role layout (block = 128 threads)
#define SCAT_CTAS ((NROWS/2 + 127) / 128)        // 782 (one int2 pair/thread)
#define COOC_CTAS (NCLASS / COOC_RPB)            // 250
#define ACC_BASE  (SCAT_CTAS + COOC_CTAS)        // 1032
#define GRID_TOT  (ACC_BASE + NCLASS)            // 2032

// Output layout (float32): [protos 256000][init 1000][cooc 1000000]
#define OUT_PROTO 0
#define OUT_INIT  (NCLASS*FEAT)
#define OUT_COOC  (NCLASS*FEAT + NCLASS)

// ---------------- device scratch (no allocation allowed) ----------------
// Invariants at kernel_launch entry (established by zero-init on call #1,
// restored by the accum CTAs / last accum CTA each run):
//   g_cursor_pad == 0, g_scat_done == 0, g_acc_done == 0
__device__ int g_cursor_pad[NCLASS * CPAD];
__device__ int g_rowidx[NCLASS * SLOTS];
__device__ int g_scat_done;
__device__ int g_acc_done;

// ---------------- single fused kernel ------------------------------------
// Roles by blockIdx (dispatch is in increasing bid order, so all scatter
// CTAs are resident before accum spinners can occupy the machine):
//   [0, 782):     scatter  — label -> padded per-class row lists
//   [782, 1032):  cooc     — smem presence-bitmask + popcount rows
//   [1032, 2032): accum    — spin on scatter-done flag, then per-class
//                            normalize+sum, EMA, write protos
// occ 7 CTAs/SM (1036 slots): accum's 1000 CTAs remain a single wave
// (the R8->R9 lesson), and the 72-reg budget absorbs index prefetch.
__global__ void __launch_bounds__(128, 7)
k_fused(const int*   __restrict__ labels,
        const int*   __restrict__ lpi,
        const float* __restrict__ cooc_in,
        const float* __restrict__ features,
        const float* __restrict__ prototypes,
        const int*   __restrict__ init_mask,
        const int*   __restrict__ step_ptr,
        float*       __restrict__ out)
{
    __shared__ __align__(16) char smraw[NCLASS * 8];   // 8000B: scol | sacc
    int t   = threadIdx.x;
    int bid = blockIdx.x;

    // ================= role: scatter =================
    if (bid < SCAT_CTAS) {
        int i = bid * 128 + t;
        if (i < NROWS / 2) {
            int2 l = __ldg(reinterpret_cast<const int2*>(labels) + i);
            int p0 = atomicAdd(&g_cursor_pad[l.x * CPAD], 1);
            int p1 = atomicAdd(&g_cursor_pad[l.y * CPAD], 1);
            int r = 2 * i;
            if (p0 < SLOTS) g_rowidx[l.x * SLOTS + p0] = r + 0;
            if (p1 < SLOTS) g_rowidx[l.y * SLOTS + p1] = r + 1;
        }
        __threadfence();            // publish stores before the release count
        __syncthreads();
        if (t == 0) atomicAdd(&g_scat_done, 1);
        return;
    }

    // ================= role: cooc =================
    if (bid < ACC_BASE) {
        unsigned long long* scol = reinterpret_cast<unsigned long long*>(smraw);
        for (int k = t; k < NCLASS; k += 128) scol[k] = 0ULL;
        __syncthreads();
        for (int k = t; k < NIMG * KPI; k += 128) {
            int img = k / KPI;
            atomicOr(&scol[__ldg(&lpi[k])], 1ULL << img);
        }
        __syncthreads();

        int i0 = (bid - SCAT_CTAS) * COOC_RPB;
        if (t < NCLASS / 8) {                 // 125 threads, 8 cols each
            int j0 = t * 8;
            unsigned long long cb[8];
            #pragma unroll
            for (int j = 0; j < 8; ++j) cb[j] = scol[j0 + j];
            #pragma unroll
            for (int rr = 0; rr < COOC_RPB; ++rr) {
                int i = i0 + rr;
                unsigned long long bi = scol[i];
                const float4* in4 = reinterpret_cast<const float4*>(cooc_in + (size_t)i * NCLASS + j0);
                float4* out4      = reinterpret_cast<float4*>(out + OUT_COOC + (size_t)i * NCLASS + j0);
                float4 v0 = __ldg(in4 + 0);
                float4 v1 = __ldg(in4 + 1);
                v0.x += (i == j0 + 0) ? 0.f : (float)__popcll(bi & cb[0]);
                v0.y += (i == j0 + 1) ? 0.f : (float)__popcll(bi & cb[1]);
                v0.z += (i == j0 + 2) ? 0.f : (float)__popcll(bi & cb[2]);
                v0.w += (i == j0 + 3) ? 0.f : (float)__popcll(bi & cb[3]);
                v1.x += (i == j0 + 4) ? 0.f : (float)__popcll(bi & cb[4]);
                v1.y += (i == j0 + 5) ? 0.f : (float)__popcll(bi & cb[5]);
                v1.z += (i == j0 + 6) ? 0.f : (float)__popcll(bi & cb[6]);
                v1.w += (i == j0 + 7) ? 0.f : (float)__popcll(bi & cb[7]);
                out4[0] = v0;
                out4[1] = v1;
            }
        }
        return;
    }

    // ================= role: accum =================
    int c    = bid - ACC_BASE;
    int warp = t >> 5;          // 0..3
    int lane = t & 31;

    // wait for all scatter CTAs (device-side dependency, no kernel boundary)
    if (t == 0) {
        while (atomicAdd(&g_scat_done, 0) < SCAT_CTAS) __nanosleep(128);
        __threadfence();        // acquire
    }
    __syncthreads();

    int count = min(g_cursor_pad[c * CPAD], SLOTS);
    const int* __restrict__ rows = &g_rowidx[c * SLOTS];

    float acc[8];
    #pragma unroll
    for (int j = 0; j < 8; ++j) acc[j] = 0.f;

    int r = warp;
    int n0 = 0, n1 = 0, n2 = 0, n3 = 0;
    bool have = (r + 12 < count);
    if (have) {
        n0 = __ldg(&rows[r]);
        n1 = __ldg(&rows[r + 4]);
        n2 = __ldg(&rows[r + 8]);
        n3 = __ldg(&rows[r + 12]);
    }
    while (have) {
        const float4* rp0 = reinterpret_cast<const float4*>(features + (size_t)n0 * FEAT);
        const float4* rp1 = reinterpret_cast<const float4*>(features + (size_t)n1 * FEAT);
        const float4* rp2 = reinterpret_cast<const float4*>(features + (size_t)n2 * FEAT);
        const float4* rp3 = reinterpret_cast<const float4*>(features + (size_t)n3 * FEAT);

        // prefetch next group's indices before the feature loads so the
        // index fetch latency overlaps feature processing
        int rn = r + 16;
        bool nh = (rn + 12 < count);
        int m0 = 0, m1 = 0, m2 = 0, m3 = 0;
        if (nh) {
            m0 = __ldg(&rows[rn]);
            m1 = __ldg(&rows[rn + 4]);
            m2 = __ldg(&rows[rn + 8]);
            m3 = __ldg(&rows[rn + 12]);
        }

        float4 a0 = __ldg(&rp0[lane * 2 + 0]);
        float4 b0 = __ldg(&rp0[lane * 2 + 1]);
        float4 a1 = __ldg(&rp1[lane * 2 + 0]);
        float4 b1 = __ldg(&rp1[lane * 2 + 1]);
        float4 a2 = __ldg(&rp2[lane * 2 + 0]);
        float4 b2 = __ldg(&rp2[lane * 2 + 1]);
        float4 a3 = __ldg(&rp3[lane * 2 + 0]);
        float4 b3 = __ldg(&rp3[lane * 2 + 1]);

        float s0 = a0.x*a0.x + a0.y*a0.y + a0.z*a0.z + a0.w*a0.w
                 + b0.x*b0.x + b0.y*b0.y + b0.z*b0.z + b0.w*b0.w;
        float s1 = a1.x*a1.x + a1.y*a1.y + a1.z*a1.z + a1.w*a1.w
                 + b1.x*b1.x + b1.y*b1.y + b1.z*b1.z + b1.w*b1.w;
        float s2 = a2.x*a2.x + a2.y*a2.y + a2.z*a2.z + a2.w*a2.w
                 + b2.x*b2.x + b2.y*b2.y + b2.z*b2.z + b2.w*b2.w;
        float s3 = a3.x*a3.x + a3.y*a3.y + a3.z*a3.z + a3.w*a3.w
                 + b3.x*b3.x + b3.y*b3.y + b3.z*b3.z + b3.w*b3.w;
        #pragma unroll
        for (int off = 16; off > 0; off >>= 1) {
            s0 += __shfl_xor_sync(0xffffffffu, s0, off);
            s1 += __shfl_xor_sync(0xffffffffu, s1, off);
            s2 += __shfl_xor_sync(0xffffffffu, s2, off);
            s3 += __shfl_xor_sync(0xffffffffu, s3, off);
        }
        float i0 = 1.0f / fmaxf(sqrtf(s0), 1e-12f);
        float i1 = 1.0f / fmaxf(sqrtf(s1), 1e-12f);
        float i2 = 1.0f / fmaxf(sqrtf(s2), 1e-12f);
        float i3 = 1.0f / fmaxf(sqrtf(s3), 1e-12f);
        acc[0] += a0.x*i0 + a1.x*i1 + a2.x*i2 + a3.x*i3;
        acc[1] += a0.y*i0 + a1.y*i1 + a2.y*i2 + a3.y*i3;
        acc[2] += a0.z*i0 + a1.z*i1 + a2.z*i2 + a3.z*i3;
        acc[3] += a0.w*i0 + a1.w*i1 + a2.w*i2 + a3.w*i3;
        acc[4] += b0.x*i0 + b1.x*i1 + b2.x*i2 + b3.x*i3;
        acc[5] += b0.y*i0 + b1.y*i1 + b2.y*i2 + b3.y*i3;
        acc[6] += b0.z*i0 + b1.z*i1 + b2.z*i2 + b3.z*i3;
        acc[7] += b0.w*i0 + b1.w*i1 + b2.w*i2 + b3.w*i3;

        r = rn; have = nh;
        n0 = m0; n1 = m1; n2 = m2; n3 = m3;
    }
    while (r < count) {
        int row = __ldg(&rows[r]);
        const float4* rp = reinterpret_cast<const float4*>(features + (size_t)row * FEAT);
        float4 a = __ldg(&rp[lane * 2 + 0]);
        float4 b = __ldg(&rp[lane * 2 + 1]);
        float s = a.x*a.x + a.y*a.y + a.z*a.z + a.w*a.w
                + b.x*b.x + b.y*b.y + b.z*b.z + b.w*b.w;
        #pragma unroll
        for (int off = 16; off > 0; off >>= 1)
            s += __shfl_xor_sync(0xffffffffu, s, off);
        float inv = 1.0f / fmaxf(sqrtf(s), 1e-12f);
        acc[0] += a.x*inv; acc[1] += a.y*inv; acc[2] += a.z*inv; acc[3] += a.w*inv;
        acc[4] += b.x*inv; acc[5] += b.y*inv; acc[6] += b.z*inv; acc[7] += b.w*inv;
        r += 4;
    }

    // combine 4 warps' partials: warp w's lane l owns cols [8l, 8l+8)
    float (*sacc)[FEAT] = reinterpret_cast<float (*)[FEAT]>(smraw);
    #pragma unroll
    for (int j = 0; j < 8; ++j) sacc[warp][lane * 8 + j] = acc[j];
    __syncthreads();

    // SAFE cleanup: barrier above guarantees all threads consumed `count`;
    // only this CTA touches g_cursor_pad[c*CPAD].
    if (t == 0) g_cursor_pad[c * CPAD] = 0;

    int   step     = step_ptr ? __ldg(step_ptr) : 5000;
    float progress = fminf(1.0f, (float)step / 2000.0f);   // WARMUP_STEPS*10
    float m        = 0.99f + (0.999f - 0.99f) * progress;

    bool present = (count > 0);
    bool inited  = (__ldg(&init_mask[c]) > 0);
    float rcount = 1.0f / fmaxf((float)count, 1.0f);

    #pragma unroll
    for (int h = 0; h < 2; ++h) {
        int col = t + h * 128;
        float sum = sacc[0][col] + sacc[1][col] + sacc[2][col] + sacc[3][col];
        float mean  = sum * rcount;
        float proto = __ldg(&prototypes[(size_t)c * FEAT + col]);
        float np;
        if (present && inited) np = m * proto + (1.0f - m) * mean;
        else if (present)      np = mean;
        else                   np = proto;
        out[OUT_PROTO + (size_t)c * FEAT + col] = np;
    }
    if (t == 0) {
        out[OUT_INIT + c] = (inited || present) ? 1.0f : 0.0f;
        // last accum CTA restores the flag invariants for the next replay
        int d = atomicAdd(&g_acc_done, 1);
        if (d == NCLASS - 1) {
            g_scat_done = 0;
            g_acc_done  = 0;
        }
    }
}

// ---------------- launch ------------------------------------------------
extern "C" void kernel_launch(void* const* d_in, const int* in_sizes, int n_in,
                              void* d_out, int out_size)
{
    const float* features   = (const float*)d_in[0];
    const int*   labels     = (const int*)  d_in[1];
    const int*   lpi        = (const int*)  d_in[2];
    const float* prototypes = (const float*)d_in[3];
    const int*   init_mask  = (const int*)  d_in[4];
    const float* cooc_in    = (const float*)d_in[5];
    const int*   step_ptr   = (n_in >= 7) ? (const int*)d_in[6] : nullptr;
    float*       out        = (float*)d_out;

    k_fused<<<GRID_TOT, 128>>>(labels, lpi, cooc_in, features,
                               prototypes, init_mask, step_ptr, out);
}

// round 11
// speedup vs baseline: 1.1060x; 1.1060x over previous
#include <cuda_runtime.h>
#include <cuda_bf16.h>
#include <cstdint>

// Problem constants
#define NROWS   200000
#define FEAT    256
#define NCLASS  1000
#define NIMG    64
#define KPI     100
#define SLOTS   512            // padded rows-per-class capacity (max actual ~270)
#define CPAD    32             // cursor padding: 1 counter per 128B L2 line
#define COOC_RPB 4
#define COOC_CTAS   (NCLASS / COOC_RPB)          // 250
#define SCAT_CTAS   ((NROWS/2 + 255) / 256)      // 391
#define K1_GRID     (COOC_CTAS + SCAT_CTAS)      // 641 -> single wave

// Output layout (float32): [protos 256000][init 1000][cooc 1000000]
#define OUT_PROTO 0
#define OUT_INIT  (NCLASS*FEAT)
#define OUT_COOC  (NCLASS*FEAT + NCLASS)

// ---------------- device scratch (no allocation allowed) ----------------
// Invariant: g_cursor_pad counters are all-zero at kernel_launch entry.
// Zero-initialized statics cover call #1; k_class_accum re-zeros each
// element AFTER the block barrier that follows all reads of it.
__device__ int g_cursor_pad[NCLASS * CPAD];
__device__ int g_rowidx[NCLASS * SLOTS];

// ---------------- K1: grid-specialized cooc | scatter ---------------------
// Different CTAs take different roles in one launch (R8: same-thread
// fusion serializes; R10: whole-pipeline fusion breaks the accum wave
// structure — this split is the sweet spot).
__global__ void __launch_bounds__(256)
k_cooc_scatter(const int* __restrict__ labels,
               const int* __restrict__ lpi,
               const float* __restrict__ cooc_in,
               float* __restrict__ out)
{
    int t   = threadIdx.x;
    int bid = blockIdx.x;

    if (bid >= COOC_CTAS) {
        // ---- scatter role: one int2 label pair per thread ----
        int i = (bid - COOC_CTAS) * 256 + t;
        if (i < NROWS / 2) {
            int2 l = __ldg(reinterpret_cast<const int2*>(labels) + i);
            int p0 = atomicAdd(&g_cursor_pad[l.x * CPAD], 1);
            int p1 = atomicAdd(&g_cursor_pad[l.y * CPAD], 1);
            int r = 2 * i;
            if (p0 < SLOTS) g_rowidx[l.x * SLOTS + p0] = r + 0;
            if (p1 < SLOTS) g_rowidx[l.y * SLOTS + p1] = r + 1;
        }
        return;
    }

    // ---- cooc role ----
    __shared__ unsigned long long scol[NCLASS];
    for (int k = t; k < NCLASS; k += 256) scol[k] = 0ULL;
    __syncthreads();
    for (int k = t; k < NIMG * KPI; k += 256) {
        int img = k / KPI;
        atomicOr(&scol[__ldg(&lpi[k])], 1ULL << img);
    }
    __syncthreads();

    int i0 = bid * COOC_RPB;
    if (t < NCLASS / 4) {
        int j0 = t * 4;
        unsigned long long c0 = scol[j0 + 0];
        unsigned long long c1 = scol[j0 + 1];
        unsigned long long c2 = scol[j0 + 2];
        unsigned long long c3 = scol[j0 + 3];
        #pragma unroll
        for (int rr = 0; rr < COOC_RPB; ++rr) {
            int i = i0 + rr;
            unsigned long long bi = scol[i];
            const float4* in4 = reinterpret_cast<const float4*>(cooc_in + (size_t)i * NCLASS) + t;
            float4 v = __ldg(in4);
            v.x += (i == j0 + 0) ? 0.f : (float)__popcll(bi & c0);
            v.y += (i == j0 + 1) ? 0.f : (float)__popcll(bi & c1);
            v.z += (i == j0 + 2) ? 0.f : (float)__popcll(bi & c2);
            v.w += (i == j0 + 3) ? 0.f : (float)__popcll(bi & c3);
            reinterpret_cast<float4*>(out + OUT_COOC + (size_t)i * NCLASS)[t] = v;
        }
    }
}

// ---------------- K2: per-class normalize+sum, EMA, write protos ---------
// 1000 CTAs (one per class), 128 threads (4 warps), 7 CTAs/SM:
// 148*7 = 1036 resident slots >= 1000 CTAs -> SINGLE WAVE (load-bearing:
// R8's 1.69-wave config capped DRAM at 52%; single wave hit 68%).
// Each warp owns whole rows (stride 4), 4 rows in flight; the NEXT
// group's row indices are prefetched before this group's feature loads so
// the L2 index fetch (~234cyc) overlaps feature processing.
__global__ void __launch_bounds__(128, 7)
k_class_accum(const float* __restrict__ features,
              const float* __restrict__ prototypes,
              const int*   __restrict__ init_mask,
              const int*   __restrict__ step_ptr,
              float*       __restrict__ out)
{
    int c    = blockIdx.x;
    int tid  = threadIdx.x;
    int warp = tid >> 5;       // 0..3
    int lane = tid & 31;

    int count = min(g_cursor_pad[c * CPAD], SLOTS);
    const int* __restrict__ rows = &g_rowidx[c * SLOTS];

    float acc[8];
    #pragma unroll
    for (int j = 0; j < 8; ++j) acc[j] = 0.f;

    int r = warp;
    int n0 = 0, n1 = 0, n2 = 0, n3 = 0;
    bool have = (r + 12 < count);
    if (have) {
        n0 = __ldg(&rows[r]);
        n1 = __ldg(&rows[r + 4]);
        n2 = __ldg(&rows[r + 8]);
        n3 = __ldg(&rows[r + 12]);
    }
    while (have) {
        const float4* rp0 = reinterpret_cast<const float4*>(features + (size_t)n0 * FEAT);
        const float4* rp1 = reinterpret_cast<const float4*>(features + (size_t)n1 * FEAT);
        const float4* rp2 = reinterpret_cast<const float4*>(features + (size_t)n2 * FEAT);
        const float4* rp3 = reinterpret_cast<const float4*>(features + (size_t)n3 * FEAT);

        // prefetch next group's indices (off the serial path)
        int rn = r + 16;
        bool nh = (rn + 12 < count);
        int m0 = 0, m1 = 0, m2 = 0, m3 = 0;
        if (nh) {
            m0 = __ldg(&rows[rn]);
            m1 = __ldg(&rows[rn + 4]);
            m2 = __ldg(&rows[rn + 8]);
            m3 = __ldg(&rows[rn + 12]);
        }

        float4 a0 = __ldg(&rp0[lane * 2 + 0]);
        float4 b0 = __ldg(&rp0[lane * 2 + 1]);
        float4 a1 = __ldg(&rp1[lane * 2 + 0]);
        float4 b1 = __ldg(&rp1[lane * 2 + 1]);
        float4 a2 = __ldg(&rp2[lane * 2 + 0]);
        float4 b2 = __ldg(&rp2[lane * 2 + 1]);
        float4 a3 = __ldg(&rp3[lane * 2 + 0]);
        float4 b3 = __ldg(&rp3[lane * 2 + 1]);

        float s0 = a0.x*a0.x + a0.y*a0.y + a0.z*a0.z + a0.w*a0.w
                 + b0.x*b0.x + b0.y*b0.y + b0.z*b0.z + b0.w*b0.w;
        float s1 = a1.x*a1.x + a1.y*a1.y + a1.z*a1.z + a1.w*a1.w
                 + b1.x*b1.x + b1.y*b1.y + b1.z*b1.z + b1.w*b1.w;
        float s2 = a2.x*a2.x + a2.y*a2.y + a2.z*a2.z + a2.w*a2.w
                 + b2.x*b2.x + b2.y*b2.y + b2.z*b2.z + b2.w*b2.w;
        float s3 = a3.x*a3.x + a3.y*a3.y + a3.z*a3.z + a3.w*a3.w
                 + b3.x*b3.x + b3.y*b3.y + b3.z*b3.z + b3.w*b3.w;
        #pragma unroll
        for (int off = 16; off > 0; off >>= 1) {
            s0 += __shfl_xor_sync(0xffffffffu, s0, off);
            s1 += __shfl_xor_sync(0xffffffffu, s1, off);
            s2 += __shfl_xor_sync(0xffffffffu, s2, off);
            s3 += __shfl_xor_sync(0xffffffffu, s3, off);
        }
        float i0 = 1.0f / fmaxf(sqrtf(s0), 1e-12f);
        float i1 = 1.0f / fmaxf(sqrtf(s1), 1e-12f);
        float i2 = 1.0f / fmaxf(sqrtf(s2), 1e-12f);
        float i3 = 1.0f / fmaxf(sqrtf(s3), 1e-12f);
        acc[0] += a0.x*i0 + a1.x*i1 + a2.x*i2 + a3.x*i3;
        acc[1] += a0.y*i0 + a1.y*i1 + a2.y*i2 + a3.y*i3;
        acc[2] += a0.z*i0 + a1.z*i1 + a2.z*i2 + a3.z*i3;
        acc[3] += a0.w*i0 + a1.w*i1 + a2.w*i2 + a3.w*i3;
        acc[4] += b0.x*i0 + b1.x*i1 + b2.x*i2 + b3.x*i3;
        acc[5] += b0.y*i0 + b1.y*i1 + b2.y*i2 + b3.y*i3;
        acc[6] += b0.z*i0 + b1.z*i1 + b2.z*i2 + b3.z*i3;
        acc[7] += b0.w*i0 + b1.w*i1 + b2.w*i2 + b3.w*i3;

        r = rn; have = nh;
        n0 = m0; n1 = m1; n2 = m2; n3 = m3;
    }
    while (r < count) {
        int row = __ldg(&rows[r]);
        const float4* rp = reinterpret_cast<const float4*>(features + (size_t)row * FEAT);
        float4 a = __ldg(&rp[lane * 2 + 0]);
        float4 b = __ldg(&rp[lane * 2 + 1]);
        float s = a.x*a.x + a.y*a.y + a.z*a.z + a.w*a.w
                + b.x*b.x + b.y*b.y + b.z*b.z + b.w*b.w;
        #pragma unroll
        for (int off = 16; off > 0; off >>= 1)
            s += __shfl_xor_sync(0xffffffffu, s, off);
        float inv = 1.0f / fmaxf(sqrtf(s), 1e-12f);
        acc[0] += a.x*inv; acc[1] += a.y*inv; acc[2] += a.z*inv; acc[3] += a.w*inv;
        acc[4] += b.x*inv; acc[5] += b.y*inv; acc[6] += b.z*inv; acc[7] += b.w*inv;
        r += 4;
    }

    // combine 4 warps' partials: warp w's lane l owns cols [8l, 8l+8)
    __shared__ float sacc[4][FEAT];
    #pragma unroll
    for (int j = 0; j < 8; ++j) sacc[warp][lane * 8 + j] = acc[j];
    __syncthreads();

    // SAFE cleanup point: barrier above guarantees every thread consumed
    // `count`; no other CTA touches g_cursor_pad[c*CPAD].
    if (tid == 0) g_cursor_pad[c * CPAD] = 0;

    int   step     = step_ptr ? __ldg(step_ptr) : 5000;
    float progress = fminf(1.0f, (float)step / 2000.0f);   // WARMUP_STEPS*10
    float m        = 0.99f + (0.999f - 0.99f) * progress;

    bool present = (count > 0);
    bool inited  = (__ldg(&init_mask[c]) > 0);
    float rcount = 1.0f / fmaxf((float)count, 1.0f);

    #pragma unroll
    for (int h = 0; h < 2; ++h) {
        int col = tid + h * 128;
        float sum = sacc[0][col] + sacc[1][col] + sacc[2][col] + sacc[3][col];
        float mean  = sum * rcount;
        float proto = __ldg(&prototypes[(size_t)c * FEAT + col]);
        float np;
        if (present && inited) np = m * proto + (1.0f - m) * mean;
        else if (present)      np = mean;
        else                   np = proto;
        out[OUT_PROTO + (size_t)c * FEAT + col] = np;
    }
    if (tid == 0)
        out[OUT_INIT + c] = (inited || present) ? 1.0f : 0.0f;
}

// ---------------- launch ------------------------------------------------
extern "C" void kernel_launch(void* const* d_in, const int* in_sizes, int n_in,
                              void* d_out, int out_size)
{
    const float* features   = (const float*)d_in[0];
    const int*   labels     = (const int*)  d_in[1];
    const int*   lpi        = (const int*)  d_in[2];
    const float* prototypes = (const float*)d_in[3];
    const int*   init_mask  = (const int*)  d_in[4];
    const float* cooc_in    = (const float*)d_in[5];
    const int*   step_ptr   = (n_in >= 7) ? (const int*)d_in[6] : nullptr;
    float*       out        = (float*)d_out;

    k_cooc_scatter<<<K1_GRID, 256>>>(labels, lpi, cooc_in, out);
    k_class_accum<<<NCLASS, 128>>>(features, prototypes, init_mask, step_ptr, out);
}